// round 14
// baseline (speedup 1.0000x reference)
#include <cuda_runtime.h>
#include <cstdint>

#define D 128
#define C 32
#define LSEQ 4096
#define BH 32
#define NCHUNK 128              // chunks per (b,h)
#define NC_TOTAL 4096           // total chunks
#define ASTR 36                 // 32x32 matrix row stride (pad 4, 16B-aligned rows)
#define RSTR 132                // prep chunk row stride
#define KSTR 128                // scan tile row stride (XOR row-swizzled)
#define VSLICE 16               // dv slice width per scan CTA
#define NSPLIT 8                // dv splits
#define USTR 20                 // 16-col matrix row stride (pad 4)

// Scratch (allocation-free rule: __device__ globals)
__device__ float g_qn[BH * LSEQ * D];
__device__ float g_kn[BH * LSEQ * D];
__device__ float g_w [BH * LSEQ * D];
__device__ float g_u [BH * LSEQ * D];
__device__ float g_attn[NC_TOTAL * C * C];

// ---------------- packed f32x2 helpers (FFMA2 path, sm_100+) ----------------
__device__ __forceinline__ unsigned long long pk2(float v) {
    unsigned long long r;
    asm("mov.b64 %0, {%1, %1};" : "=l"(r) : "f"(v));
    return r;
}
__device__ __forceinline__ unsigned long long pkf(float lo, float hi) {
    unsigned long long r;
    asm("mov.b64 %0, {%1, %2};" : "=l"(r) : "f"(lo), "f"(hi));
    return r;
}
__device__ __forceinline__ void fma2(unsigned long long& a,
                                     unsigned long long b, unsigned long long c) {
    asm("fma.rn.f32x2 %0, %1, %2, %0;" : "+l"(a) : "l"(b), "l"(c));
}
__device__ __forceinline__ float2 up2(unsigned long long a) {
    float2 f;
    asm("mov.b64 {%0, %1}, %2;" : "=f"(f.x), "=f"(f.y) : "l"(a));
    return f;
}
__device__ __forceinline__ float hadd2(unsigned long long a) {
    float2 f = up2(a); return f.x + f.y;
}
__device__ __forceinline__ void cpa16(uint32_t s, const float* g) {
    asm volatile("cp.async.cg.shared.global [%0], [%1], 16;" :: "r"(s), "l"(g));
}

// ---------------------------------------------------------------------------
// Kernel A: per-chunk preprocessing. (byte-identical to R13)
// ---------------------------------------------------------------------------
__global__ void __launch_bounds__(256, 3) prep_kernel(
    const float* __restrict__ q, const float* __restrict__ k,
    const float* __restrict__ v, const float* __restrict__ beta)
{
    extern __shared__ float s[];
    float* sqn = s;                       // 32 x RSTR
    float* skn = sqn + C * RSTR;          // 32 x 128 (XOR-swizzled chunks)
    float* skb = skn + C * 128;           // 32 x RSTR
    float* sv  = skb + C * RSTR;          // 32 x RSTR
    float* sA  = sv  + C * RSTR;          // 32 x ASTR
    float* sP  = sA  + C * ASTR;          // 16 x 17 Schur temp

    const int nc  = blockIdx.x;
    const int t   = threadIdx.x;
    const int w   = t >> 5;
    const int lid = t & 31;
    const size_t base = (size_t)nc * (C * D);

    // ---- Phase 1: normalize + scale ----
    #pragma unroll
    for (int rr = 0; rr < 4; rr++) {
        const int r = w * 4 + rr;
        const float bet = __ldg(beta + (size_t)nc * C + r);
        float4 q4 = *(const float4*)(q + base + r * D + lid * 4);
        float4 k4 = *(const float4*)(k + base + r * D + lid * 4);
        float4 v4 = *(const float4*)(v + base + r * D + lid * 4);
        float qs = q4.x*q4.x + q4.y*q4.y + q4.z*q4.z + q4.w*q4.w;
        float ks = k4.x*k4.x + k4.y*k4.y + k4.z*k4.z + k4.w*k4.w;
        #pragma unroll
        for (int o = 16; o > 0; o >>= 1) {
            qs += __shfl_xor_sync(0xffffffffu, qs, o);
            ks += __shfl_xor_sync(0xffffffffu, ks, o);
        }
        const float qr = rsqrtf(qs + 1e-6f);
        const float kr = rsqrtf(ks + 1e-6f);
        float4 qn = make_float4(q4.x*qr, q4.y*qr, q4.z*qr, q4.w*qr);
        float4 kn = make_float4(k4.x*kr, k4.y*kr, k4.z*kr, k4.w*kr);
        float4 kb = make_float4(kn.x*bet, kn.y*bet, kn.z*bet, kn.w*bet);
        float4 vb = make_float4(v4.x*bet, v4.y*bet, v4.z*bet, v4.w*bet);
        *(float4*)(sqn + r * RSTR + lid * 4) = qn;
        *(float4*)(skn + r * 128 + ((lid ^ (r & 7)) << 2)) = kn;
        *(float4*)(skb + r * RSTR + lid * 4) = kb;
        *(float4*)(sv  + r * RSTR + lid * 4) = vb;
        *(float4*)(g_qn + base + r * D + lid * 4) = qn;
        *(float4*)(g_kn + base + r * D + lid * 4) = kn;
    }
    __syncthreads();

    // ---- Phase 2: A (strict-lower, negated) and attn (lower incl diag) ----
    {
        const int j  = lid;
        const int i0 = w * 4;
        const int jx = (j & 7);
        unsigned long long A0=0,A1=0,A2=0,A3=0,T0=0,T1=0,T2=0,T3=0;
        const float* kjp = skn + j * 128;
        const float* b0p = skb + (i0+0) * RSTR;
        const float* b1p = skb + (i0+1) * RSTR;
        const float* b2p = skb + (i0+2) * RSTR;
        const float* b3p = skb + (i0+3) * RSTR;
        const float* q0p = sqn + (i0+0) * RSTR;
        const float* q1p = sqn + (i0+1) * RSTR;
        const float* q2p = sqn + (i0+2) * RSTR;
        const float* q3p = sqn + (i0+3) * RSTR;
        #pragma unroll 4
        for (int d = 0; d < D; d += 4) {
            ulonglong2 kj = *(const ulonglong2*)(kjp + ((((d >> 2) ^ jx)) << 2));
            ulonglong2 b0 = *(const ulonglong2*)(b0p + d);
            ulonglong2 b1 = *(const ulonglong2*)(b1p + d);
            ulonglong2 b2 = *(const ulonglong2*)(b2p + d);
            ulonglong2 b3 = *(const ulonglong2*)(b3p + d);
            fma2(A0, b0.x, kj.x); fma2(A0, b0.y, kj.y);
            fma2(A1, b1.x, kj.x); fma2(A1, b1.y, kj.y);
            fma2(A2, b2.x, kj.x); fma2(A2, b2.y, kj.y);
            fma2(A3, b3.x, kj.x); fma2(A3, b3.y, kj.y);
            ulonglong2 c0 = *(const ulonglong2*)(q0p + d);
            ulonglong2 c1 = *(const ulonglong2*)(q1p + d);
            ulonglong2 c2 = *(const ulonglong2*)(q2p + d);
            ulonglong2 c3 = *(const ulonglong2*)(q3p + d);
            fma2(T0, c0.x, kj.x); fma2(T0, c0.y, kj.y);
            fma2(T1, c1.x, kj.x); fma2(T1, c1.y, kj.y);
            fma2(T2, c2.x, kj.x); fma2(T2, c2.y, kj.y);
            fma2(T3, c3.x, kj.x); fma2(T3, c3.y, kj.y);
        }
        const float a0 = hadd2(A0), a1 = hadd2(A1), a2 = hadd2(A2), a3 = hadd2(A3);
        const float t0 = hadd2(T0), t1 = hadd2(T1), t2 = hadd2(T2), t3 = hadd2(T3);
        float* ga = g_attn + (size_t)nc * (C * C);
        sA[(i0+0)*ASTR + j] = (j < i0+0) ? -a0 : 0.f;
        sA[(i0+1)*ASTR + j] = (j < i0+1) ? -a1 : 0.f;
        sA[(i0+2)*ASTR + j] = (j < i0+2) ? -a2 : 0.f;
        sA[(i0+3)*ASTR + j] = (j < i0+3) ? -a3 : 0.f;
        ga[(i0+0)*C + j] = (j <= i0+0) ? t0 : 0.f;
        ga[(i0+1)*C + j] = (j <= i0+1) ? t1 : 0.f;
        ga[(i0+2)*C + j] = (j <= i0+2) ? t2 : 0.f;
        ga[(i0+3)*C + j] = (j <= i0+3) ? t3 : 0.f;
    }
    __syncthreads();

    // ---- Phase 3a: two concurrent 16x16 substitutions (warps 0 & 1) ----
    if (w < 2) {
        const int b0 = w * 16;
        const int j  = lid & 15;
        for (int i = 1; i < 16; i++) {
            float acc = 0.f;
            for (int kk = j + 1; kk < i; kk++)
                acc += sA[(b0+i)*ASTR + b0+kk] * sA[(b0+kk)*ASTR + b0+j];
            __syncwarp();
            if (lid < 16 && j < i) sA[(b0+i)*ASTR + b0+j] += acc;
            __syncwarp();
        }
        if (lid < 16) sA[(b0+j)*ASTR + b0+j] = 1.0f;
    }
    __syncthreads();

    // ---- Phase 3b: Schur combine  X21 = X22 * A21 * X11 ----
    {
        const int r = t >> 4;
        const int cc = t & 15;
        float acc = 0.f;
        #pragma unroll 4
        for (int e = 0; e < 16; e++)
            acc += sA[(16+r)*ASTR + e] * sA[e*ASTR + cc];
        sP[r * 17 + cc] = acc;
        __syncthreads();
        float acc2 = 0.f;
        #pragma unroll 4
        for (int e = 0; e < 16; e++)
            acc2 += sA[(16+r)*ASTR + 16+e] * sP[e * 17 + cc];
        sA[(16+r)*ASTR + cc] = acc2;
    }
    __syncthreads();

    // ---- Phase 4: u = inv@v , w = inv@kb ----
    {
        const int i  = t >> 3;
        const int dl = (t & 7) * 4;
        #pragma unroll
        for (int db = 0; db < 4; db++) {
            const int d = db * 32 + dl;
            unsigned long long au01=0, au23=0, aw01=0, aw23=0;
            #pragma unroll 4
            for (int j0 = 0; j0 < C; j0 += 4) {
                float4 a4 = *(const float4*)(sA + i*ASTR + j0);
                #pragma unroll
                for (int jj = 0; jj < 4; jj++) {
                    const float av = (&a4.x)[jj];
                    unsigned long long a2 = pk2(av);
                    ulonglong2 v2 = *(const ulonglong2*)(sv  + (j0+jj)*RSTR + d);
                    ulonglong2 b2 = *(const ulonglong2*)(skb + (j0+jj)*RSTR + d);
                    fma2(au01, a2, v2.x); fma2(au23, a2, v2.y);
                    fma2(aw01, a2, b2.x); fma2(aw23, a2, b2.y);
                }
            }
            float2 l, h;
            l = up2(au01); h = up2(au23);
            *(float4*)(g_u + base + i*D + d) = make_float4(l.x, l.y, h.x, h.y);
            l = up2(aw01); h = up2(aw23);
            *(float4*)(g_w + base + i*D + d) = make_float4(l.x, l.y, h.x, h.y);
        }
    }
}

// ---------------------------------------------------------------------------
// Scan kernel v2: 256 CTAs (NSPLIT=8 x BH), 2 CTAs/SM. VSLICE=16.
// Single-buffered XOR-row-swizzled tiles (q,k,w 32x128), per-chunk flow:
//   wait+sync -> phase2 (2 rows x 4 cols x 32 d per thread, 4 dq slices)
//   -> sync -> combine -> sync -> phase3 + phase4 -> sync -> prefetch next.
// Co-resident CTA hides barrier drains and load latency.
// ---------------------------------------------------------------------------
#define PMAT (C * USTR)                   // one 32x16 partial matrix (stride 20)
// tile buffer layout (floats): q[0,4096) k[4096,8192) w[8192,12288)
// u0[12288,12928) attn[12928,14080)
#define TB_U0   12288
#define TB_AT   12928
#define TB_SIZE 14080

__device__ __forceinline__ void prefetch_chunk16(
    uint32_t smb, int ci, int t, int v0,
    const float* gq, const float* gk, const float* gw,
    const float* gu, const float* ga)
{
    const size_t cb = (size_t)ci * (C * D);
    const int r  = t >> 3;              // 0..31
    const int c8 = t & 7;
    const int sr = (r >> 1) & 7;        // row swizzle
    #pragma unroll
    for (int j = 0; j < 4; j++) {
        const int g = j * 8 + c8;       // float4 group 0..31
        const uint32_t soff = (uint32_t)(r * KSTR + ((g ^ sr) << 2)) * 4u;
        const uint32_t goff = (uint32_t)(r * D + g * 4);
        cpa16(smb +          soff, gq + cb + goff);
        cpa16(smb + 16384u + soff, gk + cb + goff);
        cpa16(smb + 32768u + soff, gw + cb + goff);
    }
    if (t < 128) {
        const int uc = t >> 2, uv = (t & 3) * 4;
        cpa16(smb + (uint32_t)(TB_U0 + uc * USTR + uv) * 4u,
              gu + cb + uc * D + v0 + uv);
    }
    {
        const int ac = t >> 3, av = (t & 7) * 4;
        cpa16(smb + (uint32_t)(TB_AT + ac * ASTR + av) * 4u,
              ga + (size_t)ci * (C * C) + ac * C + av);
    }
    asm volatile("cp.async.commit_group;");
}

__global__ void __launch_bounds__(256, 2) scan_kernel(float* __restrict__ out)
{
    extern __shared__ float s[];
    float* sS  = s;                     // 128 x 16
    float* sq  = sS + D * VSLICE;       // tile buffer base
    float* sk  = sq + 4096;
    float* sw  = sq + 8192;
    float* su0 = sq + TB_U0;
    float* sat = sq + TB_AT;
    float* sui = sq + TB_SIZE;          // 32 x USTR
    float* sPQ = sui + PMAT;            // 32 x USTR
    float* sPP = sPQ + PMAT;            // 8 x PMAT (4 U, 4 Q)

    const int bh  = blockIdx.y;
    const int v0  = blockIdx.x * VSLICE;
    const int t   = threadIdx.x;
    // phase-2 mapping: 2 rows x 4 cols x 32 d per thread
    const int v4  = (t & 3) * 4;
    const int r0  = ((t >> 2) & 15) * 2;
    const int dq  = t >> 6;             // 0..3
    const int dbeg = dq * 32;
    // combine / phase-3 mapping (float2 granularity)
    const int c   = t >> 3;             // 0..31
    const int v2  = (t & 7) * 2;
    // phase-4 mapping
    const int rr4 = t >> 2;             // 0..63 (rows rr4, rr4+64)
    const int v44 = (t & 3) * 4;

    // zero S
    #pragma unroll
    for (int z = 0; z < 2; z++)
        *(float4*)(sS + (z * 256 + t) * 4) = make_float4(0.f, 0.f, 0.f, 0.f);

    const uint32_t smb = (uint32_t)__cvta_generic_to_shared(sq);

    const size_t bhb = (size_t)bh * LSEQ * D;
    const float* gq = g_qn + bhb;
    const float* gk = g_kn + bhb;
    const float* gw = g_w  + bhb;
    const float* gu = g_u  + bhb;
    const float* ga = g_attn + (size_t)bh * NCHUNK * (C * C);

    prefetch_chunk16(smb, 0, t, v0, gq, gk, gw, gu, ga);

    const int sr0 = (r0 >> 1) & 7;      // swizzle for both r0 and r0+1

    for (int ci = 0; ci < NCHUNK; ci++) {
        asm volatile("cp.async.wait_group 0;");
        __syncthreads();                // tiles ready + prev S update done

        // ---- phase 2: aU/aQ over d in [dbeg,dbeg+32), rows r0,r0+1 ----
        unsigned long long aU0x=0,aU0y=0,aU1x=0,aU1y=0;
        unsigned long long aQ0x=0,aQ0y=0,aQ1x=0,aQ1y=0;
        {
            const float* wA = sw + r0 * KSTR;
            const float* wB = sw + (r0 + 1) * KSTR;
            const float* qA = sq + r0 * KSTR;
            const float* qB = sq + (r0 + 1) * KSTR;
            #pragma unroll
            for (int dgi = 0; dgi < 8; dgi++) {
                const int gg = (((dq * 8 + dgi) ^ sr0) << 2);
                float4 wv0 = *(const float4*)(wA + gg);
                float4 wv1 = *(const float4*)(wB + gg);
                float4 qv0 = *(const float4*)(qA + gg);
                float4 qv1 = *(const float4*)(qB + gg);
                const float* Sp = sS + (dbeg + dgi * 4) * VSLICE + v4;
                #pragma unroll
                for (int i = 0; i < 4; i++) {
                    ulonglong2 S2 = *(const ulonglong2*)(Sp + i * VSLICE);
                    unsigned long long w0 = pk2((&wv0.x)[i]);
                    unsigned long long w1 = pk2((&wv1.x)[i]);
                    unsigned long long q0 = pk2((&qv0.x)[i]);
                    unsigned long long q1 = pk2((&qv1.x)[i]);
                    fma2(aU0x, w0, S2.x); fma2(aU0y, w0, S2.y);
                    fma2(aU1x, w1, S2.x); fma2(aU1y, w1, S2.y);
                    fma2(aQ0x, q0, S2.x); fma2(aQ0y, q0, S2.y);
                    fma2(aQ1x, q1, S2.x); fma2(aQ1y, q1, S2.y);
                }
            }
        }
        {
            float* PU = sPP + dq * PMAT;
            float* PQ = sPP + (4 + dq) * PMAT;
            float2 l, h;
            l = up2(aU0x); h = up2(aU0y);
            *(float4*)(PU + r0 * USTR + v4) = make_float4(l.x, l.y, h.x, h.y);
            l = up2(aU1x); h = up2(aU1y);
            *(float4*)(PU + (r0 + 1) * USTR + v4) = make_float4(l.x, l.y, h.x, h.y);
            l = up2(aQ0x); h = up2(aQ0y);
            *(float4*)(PQ + r0 * USTR + v4) = make_float4(l.x, l.y, h.x, h.y);
            l = up2(aQ1x); h = up2(aQ1y);
            *(float4*)(PQ + (r0 + 1) * USTR + v4) = make_float4(l.x, l.y, h.x, h.y);
        }
        __syncthreads();

        // ---- combine: u_i and q@S (float2 per thread) ----
        {
            float2 u0 = *(const float2*)(su0 + c * USTR + v2);
            float sUx = 0.f, sUy = 0.f, sQx = 0.f, sQy = 0.f;
            #pragma unroll
            for (int p = 0; p < 4; p++) {
                float2 pu = *(const float2*)(sPP + p * PMAT + c * USTR + v2);
                float2 pq = *(const float2*)(sPP + (4 + p) * PMAT + c * USTR + v2);
                sUx += pu.x; sUy += pu.y;
                sQx += pq.x; sQy += pq.y;
            }
            *(float2*)(sui + c * USTR + v2) = make_float2(u0.x - sUx, u0.y - sUy);
            *(float2*)(sPQ + c * USTR + v2) = make_float2(sQx, sQy);
        }
        __syncthreads();

        // ---- phase 3: out = q@S + attn @ u_i (float2 per thread) ----
        {
            float2 a0 = *(const float2*)(sPQ + c * USTR + v2);
            unsigned long long o = pkf(a0.x, a0.y);
            #pragma unroll 8
            for (int e = 0; e < C; e++) {
                unsigned long long a2 = pk2(sat[c * ASTR + e]);
                unsigned long long u2 = *(const unsigned long long*)(sui + e * USTR + v2);
                fma2(o, a2, u2);
            }
            float2 res = up2(o);
            *(float2*)(out + bhb + (size_t)ci * (C * D) + c * D + v0 + v2) = res;
        }

        // ---- phase 4: S[d,v] += sum_e k[e,d]*u_i[e,v], rows rr4, rr4+64 ----
        {
            unsigned long long A0=0, A1=0, A2=0, A3=0;
            const int gb = rr4 >> 2, rl = rr4 & 3;
            #pragma unroll 4
            for (int e = 0; e < C; e++) {
                ulonglong2 u2 = *(const ulonglong2*)(sui + e * USTR + v44);
                const float* krow = sk + e * KSTR;
                const int bidx = (((gb ^ ((e >> 1) & 7)) << 2)) + rl;
                unsigned long long k0 = pk2(krow[bidx]);
                unsigned long long k1 = pk2(krow[bidx + 64]);
                fma2(A0, k0, u2.x); fma2(A1, k0, u2.y);
                fma2(A2, k1, u2.x); fma2(A3, k1, u2.y);
            }
            float2 l, h;
            float4* p0 = (float4*)(sS + rr4 * VSLICE + v44);
            float4* p1 = (float4*)(sS + (rr4 + 64) * VSLICE + v44);
            float4 t0 = *p0, t1 = *p1;
            l = up2(A0); h = up2(A1);
            t0.x += l.x; t0.y += l.y; t0.z += h.x; t0.w += h.y;
            l = up2(A2); h = up2(A3);
            t1.x += l.x; t1.y += l.y; t1.z += h.x; t1.w += h.y;
            *p0 = t0; *p1 = t1;
        }
        __syncthreads();                // all reads of tile buffer done

        if (ci + 1 < NCHUNK)
            prefetch_chunk16(smb, ci + 1, t, v0, gq, gk, gw, gu, ga);
    }
}

// ---------------------------------------------------------------------------
extern "C" void kernel_launch(void* const* d_in, const int* in_sizes, int n_in,
                              void* d_out, int out_size)
{
    const float* q    = (const float*)d_in[0];
    const float* k    = (const float*)d_in[1];
    const float* v    = (const float*)d_in[2];
    const float* beta = (const float*)d_in[3];
    float* out = (float*)d_out;

    const size_t smemA = (size_t)(3 * C * RSTR + C * 128 + C * ASTR + 16 * 17)
                         * sizeof(float);
    const size_t smemB = (size_t)(D * VSLICE + TB_SIZE + 10 * PMAT)
                         * sizeof(float);

    cudaFuncSetAttribute(prep_kernel, cudaFuncAttributeMaxDynamicSharedMemorySize,
                         (int)smemA);
    cudaFuncSetAttribute(scan_kernel, cudaFuncAttributeMaxDynamicSharedMemorySize,
                         (int)smemB);

    prep_kernel<<<NC_TOTAL, 256, smemA>>>(q, k, v, beta);
    scan_kernel<<<dim3(NSPLIT, BH), 256, smemB>>>(out);
}

// round 15
// speedup vs baseline: 1.3418x; 1.3418x over previous
#include <cuda_runtime.h>
#include <cstdint>

#define D 128
#define C 32
#define LSEQ 4096
#define BH 32
#define NCHUNK 128              // chunks per (b,h)
#define NC_TOTAL 4096           // total chunks
#define ASTR 36                 // 32x32 matrix row stride (pad 4, 16B-aligned rows)
#define RSTR 132                // 32x128 chunk row stride (pad 4, keeps 16B align)
#define KTSTR 36                // kT tile row stride (128 rows x 32 cols, pad 4)
#define VSLICE 32               // dv slice width per scan CTA
#define NSPLIT 4                // dv splits

// Scratch (allocation-free rule: __device__ globals)
// g_kn holds k TRANSPOSED per chunk: [chunk][d 0..127][row 0..31]
__device__ float g_qn[BH * LSEQ * D];
__device__ float g_kn[BH * LSEQ * D];
__device__ float g_w [BH * LSEQ * D];
__device__ float g_u [BH * LSEQ * D];
__device__ float g_attn[NC_TOTAL * C * C];

// ---------------- packed f32x2 helpers (FFMA2 path, sm_100+) ----------------
__device__ __forceinline__ unsigned long long pk2(float v) {
    unsigned long long r;
    asm("mov.b64 %0, {%1, %1};" : "=l"(r) : "f"(v));
    return r;
}
__device__ __forceinline__ unsigned long long pkf(float lo, float hi) {
    unsigned long long r;
    asm("mov.b64 %0, {%1, %2};" : "=l"(r) : "f"(lo), "f"(hi));
    return r;
}
__device__ __forceinline__ void fma2(unsigned long long& a,
                                     unsigned long long b, unsigned long long c) {
    asm("fma.rn.f32x2 %0, %1, %2, %0;" : "+l"(a) : "l"(b), "l"(c));
}
__device__ __forceinline__ float2 up2(unsigned long long a) {
    float2 f;
    asm("mov.b64 {%0, %1}, %2;" : "=f"(f.x), "=f"(f.y) : "l"(a));
    return f;
}
__device__ __forceinline__ float hadd2(unsigned long long a) {
    float2 f = up2(a); return f.x + f.y;
}
__device__ __forceinline__ void cpa16(uint32_t s, const float* g) {
    asm volatile("cp.async.cg.shared.global [%0], [%1], 16;" :: "r"(s), "l"(g));
}

// ---------------------------------------------------------------------------
// Kernel A: per-chunk preprocessing (R13 logic + k-transpose store).
// ---------------------------------------------------------------------------
__global__ void __launch_bounds__(256, 3) prep_kernel(
    const float* __restrict__ q, const float* __restrict__ k,
    const float* __restrict__ v, const float* __restrict__ beta)
{
    extern __shared__ float s[];
    float* sqn = s;                       // 32 x RSTR
    float* skn = sqn + C * RSTR;          // 32 x 128 (XOR-swizzled chunks)
    float* skb = skn + C * 128;           // 32 x RSTR
    float* sv  = skb + C * RSTR;          // 32 x RSTR
    float* sA  = sv  + C * RSTR;          // 32 x ASTR
    float* sP  = sA  + C * ASTR;          // 16 x 17 Schur temp

    const int nc  = blockIdx.x;
    const int t   = threadIdx.x;
    const int w   = t >> 5;
    const int lid = t & 31;
    const size_t base = (size_t)nc * (C * D);

    // ---- Phase 1: normalize + scale ----
    #pragma unroll
    for (int rr = 0; rr < 4; rr++) {
        const int r = w * 4 + rr;
        const float bet = __ldg(beta + (size_t)nc * C + r);
        float4 q4 = *(const float4*)(q + base + r * D + lid * 4);
        float4 k4 = *(const float4*)(k + base + r * D + lid * 4);
        float4 v4 = *(const float4*)(v + base + r * D + lid * 4);
        float qs = q4.x*q4.x + q4.y*q4.y + q4.z*q4.z + q4.w*q4.w;
        float ks = k4.x*k4.x + k4.y*k4.y + k4.z*k4.z + k4.w*k4.w;
        #pragma unroll
        for (int o = 16; o > 0; o >>= 1) {
            qs += __shfl_xor_sync(0xffffffffu, qs, o);
            ks += __shfl_xor_sync(0xffffffffu, ks, o);
        }
        const float qr = rsqrtf(qs + 1e-6f);
        const float kr = rsqrtf(ks + 1e-6f);
        float4 qn = make_float4(q4.x*qr, q4.y*qr, q4.z*qr, q4.w*qr);
        float4 kn = make_float4(k4.x*kr, k4.y*kr, k4.z*kr, k4.w*kr);
        float4 kb = make_float4(kn.x*bet, kn.y*bet, kn.z*bet, kn.w*bet);
        float4 vb = make_float4(v4.x*bet, v4.y*bet, v4.z*bet, v4.w*bet);
        *(float4*)(sqn + r * RSTR + lid * 4) = qn;
        *(float4*)(skn + r * 128 + ((lid ^ (r & 7)) << 2)) = kn;
        *(float4*)(skb + r * RSTR + lid * 4) = kb;
        *(float4*)(sv  + r * RSTR + lid * 4) = vb;
        *(float4*)(g_qn + base + r * D + lid * 4) = qn;
        // NOTE: g_kn is now written transposed (after phase 2)
    }
    __syncthreads();

    // ---- Phase 2: A (strict-lower, negated) and attn (lower incl diag) ----
    {
        const int j  = lid;
        const int i0 = w * 4;
        const int jx = (j & 7);
        unsigned long long A0=0,A1=0,A2=0,A3=0,T0=0,T1=0,T2=0,T3=0;
        const float* kjp = skn + j * 128;
        const float* b0p = skb + (i0+0) * RSTR;
        const float* b1p = skb + (i0+1) * RSTR;
        const float* b2p = skb + (i0+2) * RSTR;
        const float* b3p = skb + (i0+3) * RSTR;
        const float* q0p = sqn + (i0+0) * RSTR;
        const float* q1p = sqn + (i0+1) * RSTR;
        const float* q2p = sqn + (i0+2) * RSTR;
        const float* q3p = sqn + (i0+3) * RSTR;
        #pragma unroll 4
        for (int d = 0; d < D; d += 4) {
            ulonglong2 kj = *(const ulonglong2*)(kjp + ((((d >> 2) ^ jx)) << 2));
            ulonglong2 b0 = *(const ulonglong2*)(b0p + d);
            ulonglong2 b1 = *(const ulonglong2*)(b1p + d);
            ulonglong2 b2 = *(const ulonglong2*)(b2p + d);
            ulonglong2 b3 = *(const ulonglong2*)(b3p + d);
            fma2(A0, b0.x, kj.x); fma2(A0, b0.y, kj.y);
            fma2(A1, b1.x, kj.x); fma2(A1, b1.y, kj.y);
            fma2(A2, b2.x, kj.x); fma2(A2, b2.y, kj.y);
            fma2(A3, b3.x, kj.x); fma2(A3, b3.y, kj.y);
            ulonglong2 c0 = *(const ulonglong2*)(q0p + d);
            ulonglong2 c1 = *(const ulonglong2*)(q1p + d);
            ulonglong2 c2 = *(const ulonglong2*)(q2p + d);
            ulonglong2 c3 = *(const ulonglong2*)(q3p + d);
            fma2(T0, c0.x, kj.x); fma2(T0, c0.y, kj.y);
            fma2(T1, c1.x, kj.x); fma2(T1, c1.y, kj.y);
            fma2(T2, c2.x, kj.x); fma2(T2, c2.y, kj.y);
            fma2(T3, c3.x, kj.x); fma2(T3, c3.y, kj.y);
        }
        const float a0 = hadd2(A0), a1 = hadd2(A1), a2 = hadd2(A2), a3 = hadd2(A3);
        const float t0 = hadd2(T0), t1 = hadd2(T1), t2 = hadd2(T2), t3 = hadd2(T3);
        float* ga = g_attn + (size_t)nc * (C * C);
        sA[(i0+0)*ASTR + j] = (j < i0+0) ? -a0 : 0.f;
        sA[(i0+1)*ASTR + j] = (j < i0+1) ? -a1 : 0.f;
        sA[(i0+2)*ASTR + j] = (j < i0+2) ? -a2 : 0.f;
        sA[(i0+3)*ASTR + j] = (j < i0+3) ? -a3 : 0.f;
        ga[(i0+0)*C + j] = (j <= i0+0) ? t0 : 0.f;
        ga[(i0+1)*C + j] = (j <= i0+1) ? t1 : 0.f;
        ga[(i0+2)*C + j] = (j <= i0+2) ? t2 : 0.f;
        ga[(i0+3)*C + j] = (j <= i0+3) ? t3 : 0.f;
    }

    // ---- k transpose store: g_kn[chunk][d][r] = kn[r][d] (coalesced STG) ----
    {
        const int r4 = (t & 7) * 4;
        const int d0 = t >> 3;              // 0..31
        #pragma unroll
        for (int i = 0; i < 4; i++) {
            const int d = d0 + 32 * i;
            const int g = d >> 2, lo = d & 3;
            float4 kk;
            kk.x = skn[(r4+0) * 128 + ((g ^ ((r4+0) & 7)) << 2) + lo];
            kk.y = skn[(r4+1) * 128 + ((g ^ ((r4+1) & 7)) << 2) + lo];
            kk.z = skn[(r4+2) * 128 + ((g ^ ((r4+2) & 7)) << 2) + lo];
            kk.w = skn[(r4+3) * 128 + ((g ^ ((r4+3) & 7)) << 2) + lo];
            *(float4*)(g_kn + base + d * C + r4) = kk;
        }
    }
    __syncthreads();

    // ---- Phase 3a: two concurrent 16x16 substitutions (warps 0 & 1) ----
    if (w < 2) {
        const int b0 = w * 16;
        const int j  = lid & 15;
        for (int i = 1; i < 16; i++) {
            float acc = 0.f;
            for (int kk = j + 1; kk < i; kk++)
                acc += sA[(b0+i)*ASTR + b0+kk] * sA[(b0+kk)*ASTR + b0+j];
            __syncwarp();
            if (lid < 16 && j < i) sA[(b0+i)*ASTR + b0+j] += acc;
            __syncwarp();
        }
        if (lid < 16) sA[(b0+j)*ASTR + b0+j] = 1.0f;
    }
    __syncthreads();

    // ---- Phase 3b: Schur combine  X21 = X22 * A21 * X11 ----
    {
        const int r = t >> 4;
        const int cc = t & 15;
        float acc = 0.f;
        #pragma unroll 4
        for (int e = 0; e < 16; e++)
            acc += sA[(16+r)*ASTR + e] * sA[e*ASTR + cc];
        sP[r * 17 + cc] = acc;
        __syncthreads();
        float acc2 = 0.f;
        #pragma unroll 4
        for (int e = 0; e < 16; e++)
            acc2 += sA[(16+r)*ASTR + 16+e] * sP[e * 17 + cc];
        sA[(16+r)*ASTR + cc] = acc2;
    }
    __syncthreads();

    // ---- Phase 4: u = inv@v , w = inv@kb ----
    {
        const int i  = t >> 3;
        const int dl = (t & 7) * 4;
        #pragma unroll
        for (int db = 0; db < 4; db++) {
            const int d = db * 32 + dl;
            unsigned long long au01=0, au23=0, aw01=0, aw23=0;
            #pragma unroll 4
            for (int j0 = 0; j0 < C; j0 += 4) {
                float4 a4 = *(const float4*)(sA + i*ASTR + j0);
                #pragma unroll
                for (int jj = 0; jj < 4; jj++) {
                    const float av = (&a4.x)[jj];
                    unsigned long long a2 = pk2(av);
                    ulonglong2 v2 = *(const ulonglong2*)(sv  + (j0+jj)*RSTR + d);
                    ulonglong2 b2 = *(const ulonglong2*)(skb + (j0+jj)*RSTR + d);
                    fma2(au01, a2, v2.x); fma2(au23, a2, v2.y);
                    fma2(aw01, a2, b2.x); fma2(aw23, a2, b2.y);
                }
            }
            float2 l, h;
            l = up2(au01); h = up2(au23);
            *(float4*)(g_u + base + i*D + d) = make_float4(l.x, l.y, h.x, h.y);
            l = up2(aw01); h = up2(aw23);
            *(float4*)(g_w + base + i*D + d) = make_float4(l.x, l.y, h.x, h.y);
        }
    }
}

// ---------------------------------------------------------------------------
// Scan kernel: R11 structure + (a) transposed-k tiles for the S update,
// (b) fused phase 3+4 (single e-loop; sui loaded once, two accum chains).
// ---------------------------------------------------------------------------
// tile buffer offsets (floats): q | kT(128x36) | w | u0 | attn
#define OQ  0
#define OKT (C * RSTR)                       // 4224
#define OW  (OKT + D * KTSTR)                // 8832
#define OU0 (OW + C * RSTR)                  // 13056
#define OAT (OU0 + C * ASTR)                 // 14208
#define SBUF (OAT + C * ASTR)                // 15360
#define PMAT (C * ASTR)                      // one 32x32 partial matrix

__device__ __forceinline__ void prefetch_chunk(
    uint32_t smb, int ci, int w, int lid, int t, int c, int v4, int v0,
    const float* gq, const float* gkT, const float* gw,
    const float* gu, const float* ga)
{
    const size_t cb = (size_t)ci * (C * D);
    #pragma unroll
    for (int rr = 0; rr < 4; rr++) {
        const int r = w * 4 + rr;
        const uint32_t off = (uint32_t)(r * RSTR + lid * 4) * 4u;
        cpa16(smb + (uint32_t)OQ * 4u + off, gq + cb + r * D + lid * 4);
        cpa16(smb + (uint32_t)OW * 4u + off, gw + cb + r * D + lid * 4);
    }
    #pragma unroll
    for (int i = 0; i < 4; i++) {
        const int idx = t + 256 * i;
        const int row = idx >> 3;            // 0..127
        const int c4  = (idx & 7) * 4;
        cpa16(smb + (uint32_t)(OKT + row * KTSTR + c4) * 4u,
              gkT + cb + row * C + c4);
    }
    cpa16(smb + (uint32_t)(OU0 + c * ASTR + v4) * 4u, gu + cb + c * D + v0 + v4);
    cpa16(smb + (uint32_t)(OAT + c * ASTR + v4) * 4u,
          ga + (size_t)ci * (C * C) + c * C + v4);
    asm volatile("cp.async.commit_group;");
}

__global__ void __launch_bounds__(256, 1) scan_kernel(float* __restrict__ out)
{
    extern __shared__ float s[];
    float* sS  = s;                         // 128 x VSLICE
    float* sb0 = sS + D * VSLICE;
    float* sb1 = sb0 + SBUF;
    float* sui = sb1 + SBUF;                // 32 x ASTR
    float* sPQ = sui + C * ASTR;            // 32 x ASTR (final q@S)
    float* sPP = sPQ + C * ASTR;            // 8 x PMAT partial matrices (4 U, 4 Q)

    const int bh  = blockIdx.y;
    const int v0  = blockIdx.x * VSLICE;
    const int t   = threadIdx.x;
    const int w   = t >> 5;
    const int lid = t & 31;
    const int v4  = (t & 7) * 4;
    const int r0  = ((t >> 3) & 7) * 4;     // rows r0..r0+3
    const int dq  = t >> 6;                 // d quarter 0..3
    const int c   = t >> 3;

    #pragma unroll
    for (int rr = 0; rr < 4; rr++)
        *(float4*)(sS + (rr * 256 + t) * 4) = make_float4(0.f, 0.f, 0.f, 0.f);

    const uint32_t smb0 = (uint32_t)__cvta_generic_to_shared(sb0);
    const uint32_t smb1 = (uint32_t)__cvta_generic_to_shared(sb1);

    const size_t bhb = (size_t)bh * LSEQ * D;
    const float* gq  = g_qn + bhb;
    const float* gkT = g_kn + bhb;
    const float* gw  = g_w  + bhb;
    const float* gu  = g_u  + bhb;
    const float* ga  = g_attn + (size_t)bh * NCHUNK * (C * C);

    prefetch_chunk(smb0, 0, w, lid, t, c, v4, v0, gq, gkT, gw, gu, ga);

    for (int ci = 0; ci < NCHUNK; ci++) {
        float* B = (ci & 1) ? sb1 : sb0;
        const uint32_t smn = (ci & 1) ? smb0 : smb1;
        const float* sq  = B + OQ;
        const float* skT = B + OKT;
        const float* sw  = B + OW;
        const float* su0 = B + OU0;
        const float* sat = B + OAT;

        asm volatile("cp.async.wait_group 0;");
        __syncthreads();                    // tiles ready + prev S update done

        const int cn = (ci + 1 < NCHUNK) ? ci + 1 : ci;
        prefetch_chunk(smn, cn, w, lid, t, c, v4, v0, gq, gkT, gw, gu, ga);

        // ---- phase 2: quarter-d GEMV, 4 rows/thread; ALL quarters store ----
        {
            unsigned long long aU[4][2], aQ[4][2];
            #pragma unroll
            for (int r = 0; r < 4; r++) {
                aU[r][0]=0; aU[r][1]=0; aQ[r][0]=0; aQ[r][1]=0;
            }
            const int dbeg = dq * 32;
            const float* wp = sw + dbeg;
            const float* qp = sq + dbeg;
            const float* Sp = sS + dbeg * VSLICE + v4;
            #pragma unroll 2
            for (int dg = 0; dg < 32; dg += 4) {
                float4 wv[4], qv[4];
                #pragma unroll
                for (int r = 0; r < 4; r++) {
                    wv[r] = *(const float4*)(wp + (r0 + r) * RSTR + dg);
                    qv[r] = *(const float4*)(qp + (r0 + r) * RSTR + dg);
                }
                #pragma unroll
                for (int i = 0; i < 4; i++) {
                    ulonglong2 S2 = *(const ulonglong2*)(Sp + (dg + i) * VSLICE);
                    #pragma unroll
                    for (int r = 0; r < 4; r++) {
                        unsigned long long w2 = pk2((&wv[r].x)[i]);
                        unsigned long long q2 = pk2((&qv[r].x)[i]);
                        fma2(aU[r][0], w2, S2.x); fma2(aU[r][1], w2, S2.y);
                        fma2(aQ[r][0], q2, S2.x); fma2(aQ[r][1], q2, S2.y);
                    }
                }
            }
            float* PU = sPP + dq * PMAT;
            float* PQ = sPP + (4 + dq) * PMAT;
            #pragma unroll
            for (int r = 0; r < 4; r++) {
                float2 l, h;
                l = up2(aU[r][0]); h = up2(aU[r][1]);
                *(float4*)(PU + (r0 + r) * ASTR + v4) = make_float4(l.x, l.y, h.x, h.y);
                l = up2(aQ[r][0]); h = up2(aQ[r][1]);
                *(float4*)(PQ + (r0 + r) * ASTR + v4) = make_float4(l.x, l.y, h.x, h.y);
            }
        }
        __syncthreads();

        // ---- combine (ALL 256 threads): one (c, v4) each ----
        {
            float4 u0 = *(const float4*)(su0 + c * ASTR + v4);
            float4 aU = make_float4(0.f,0.f,0.f,0.f);
            float4 aQ = make_float4(0.f,0.f,0.f,0.f);
            #pragma unroll
            for (int p = 0; p < 4; p++) {
                float4 pu = *(const float4*)(sPP + p * PMAT + c * ASTR + v4);
                float4 pq = *(const float4*)(sPP + (4+p) * PMAT + c * ASTR + v4);
                aU.x += pu.x; aU.y += pu.y; aU.z += pu.z; aU.w += pu.w;
                aQ.x += pq.x; aQ.y += pq.y; aQ.z += pq.z; aQ.w += pq.w;
            }
            *(float4*)(sui + c * ASTR + v4) = make_float4(
                u0.x - aU.x, u0.y - aU.y, u0.z - aU.z, u0.w - aU.w);
            *(float4*)(sPQ + c * ASTR + v4) = aQ;
        }
        __syncthreads();

        // ---- fused phase 3+4: one e-loop; out and S accumulate together ----
        {
            float4 a0 = *(const float4*)(sPQ + c * ASTR + v4);
            unsigned long long o01 = pkf(a0.x, a0.y);
            unsigned long long o23 = pkf(a0.z, a0.w);
            unsigned long long A0=0,A1=0,A2=0,A3=0,A4=0,A5=0,A6=0,A7=0;
            #pragma unroll 2
            for (int e4 = 0; e4 < C; e4 += 4) {
                float4 kv0 = *(const float4*)(skT + (c      ) * KTSTR + e4);
                float4 kv1 = *(const float4*)(skT + (c +  32) * KTSTR + e4);
                float4 kv2 = *(const float4*)(skT + (c +  64) * KTSTR + e4);
                float4 kv3 = *(const float4*)(skT + (c +  96) * KTSTR + e4);
                #pragma unroll
                for (int ee = 0; ee < 4; ee++) {
                    const int e = e4 + ee;
                    ulonglong2 u2 = *(const ulonglong2*)(sui + e * ASTR + v4);
                    unsigned long long a2 = pk2(sat[c * ASTR + e]);
                    fma2(o01, a2, u2.x); fma2(o23, a2, u2.y);
                    unsigned long long k0 = pk2((&kv0.x)[ee]);
                    unsigned long long k1 = pk2((&kv1.x)[ee]);
                    unsigned long long k2 = pk2((&kv2.x)[ee]);
                    unsigned long long k3 = pk2((&kv3.x)[ee]);
                    fma2(A0, k0, u2.x); fma2(A1, k0, u2.y);
                    fma2(A2, k1, u2.x); fma2(A3, k1, u2.y);
                    fma2(A4, k2, u2.x); fma2(A5, k2, u2.y);
                    fma2(A6, k3, u2.x); fma2(A7, k3, u2.y);
                }
            }
            {
                float2 l = up2(o01), h = up2(o23);
                *(float4*)(out + bhb + (size_t)ci * (C * D) + c * D + v0 + v4) =
                    make_float4(l.x, l.y, h.x, h.y);
            }
            float2 l, h;
            float4* p0 = (float4*)(sS + (c      ) * VSLICE + v4);
            float4* p1 = (float4*)(sS + (c +  32) * VSLICE + v4);
            float4* p2 = (float4*)(sS + (c +  64) * VSLICE + v4);
            float4* p3 = (float4*)(sS + (c +  96) * VSLICE + v4);
            float4 t0 = *p0, t1 = *p1, t2 = *p2, t3 = *p3;
            l = up2(A0); h = up2(A1);
            t0.x += l.x; t0.y += l.y; t0.z += h.x; t0.w += h.y;
            l = up2(A2); h = up2(A3);
            t1.x += l.x; t1.y += l.y; t1.z += h.x; t1.w += h.y;
            l = up2(A4); h = up2(A5);
            t2.x += l.x; t2.y += l.y; t2.z += h.x; t2.w += h.y;
            l = up2(A6); h = up2(A7);
            t3.x += l.x; t3.y += l.y; t3.z += h.x; t3.w += h.y;
            *p0 = t0; *p1 = t1; *p2 = t2; *p3 = t3;
        }
    }
}

// ---------------------------------------------------------------------------
extern "C" void kernel_launch(void* const* d_in, const int* in_sizes, int n_in,
                              void* d_out, int out_size)
{
    const float* q    = (const float*)d_in[0];
    const float* k    = (const float*)d_in[1];
    const float* v    = (const float*)d_in[2];
    const float* beta = (const float*)d_in[3];
    float* out = (float*)d_out;

    const size_t smemA = (size_t)(3 * C * RSTR + C * 128 + C * ASTR + 16 * 17)
                         * sizeof(float);
    const size_t smemB = (size_t)(D * VSLICE + 2 * SBUF + 2 * C * ASTR + 8 * PMAT)
                         * sizeof(float);

    cudaFuncSetAttribute(prep_kernel, cudaFuncAttributeMaxDynamicSharedMemorySize,
                         (int)smemA);
    cudaFuncSetAttribute(scan_kernel, cudaFuncAttributeMaxDynamicSharedMemorySize,
                         (int)smemB);

    prep_kernel<<<NC_TOTAL, 256, smemA>>>(q, k, v, beta);
    scan_kernel<<<dim3(NSPLIT, BH), 256, smemB>>>(out);
}

// round 16
// speedup vs baseline: 1.3497x; 1.0059x over previous
#include <cuda_runtime.h>
#include <cstdint>

#define D 128
#define C 32
#define LSEQ 4096
#define BH 32
#define NCHUNK 128              // chunks per (b,h)
#define NC_TOTAL 4096           // total chunks
#define ASTR 36                 // 32x32 matrix row stride (pad 4, 16B-aligned rows)
#define RSTR 132                // 32x128 chunk row stride (pad 4, keeps 16B align)
#define KTSTR 36                // kT tile row stride (128 rows x 32 cols, pad 4)
#define VSLICE 32               // dv slice width per scan CTA
#define NSPLIT 4                // dv splits

// Scratch (allocation-free rule: __device__ globals)
// g_kn holds k TRANSPOSED per chunk: [chunk][d 0..127][row 0..31]
__device__ float g_qn[BH * LSEQ * D];
__device__ float g_kn[BH * LSEQ * D];
__device__ float g_w [BH * LSEQ * D];
__device__ float g_u [BH * LSEQ * D];
__device__ float g_attn[NC_TOTAL * C * C];

// ---------------- packed f32x2 helpers (FFMA2 path, sm_100+) ----------------
__device__ __forceinline__ unsigned long long pk2(float v) {
    unsigned long long r;
    asm("mov.b64 %0, {%1, %1};" : "=l"(r) : "f"(v));
    return r;
}
__device__ __forceinline__ unsigned long long pkf(float lo, float hi) {
    unsigned long long r;
    asm("mov.b64 %0, {%1, %2};" : "=l"(r) : "f"(lo), "f"(hi));
    return r;
}
__device__ __forceinline__ void fma2(unsigned long long& a,
                                     unsigned long long b, unsigned long long c) {
    asm("fma.rn.f32x2 %0, %1, %2, %0;" : "+l"(a) : "l"(b), "l"(c));
}
__device__ __forceinline__ float2 up2(unsigned long long a) {
    float2 f;
    asm("mov.b64 {%0, %1}, %2;" : "=f"(f.x), "=f"(f.y) : "l"(a));
    return f;
}
__device__ __forceinline__ float hadd2(unsigned long long a) {
    float2 f = up2(a); return f.x + f.y;
}
__device__ __forceinline__ void cpa16(uint32_t s, const float* g) {
    asm volatile("cp.async.cg.shared.global [%0], [%1], 16;" :: "r"(s), "l"(g));
}

// ---------------------------------------------------------------------------
// Kernel A: per-chunk preprocessing (R15 logic; transpose overlapped with 3a).
// ---------------------------------------------------------------------------
__global__ void __launch_bounds__(256, 3) prep_kernel(
    const float* __restrict__ q, const float* __restrict__ k,
    const float* __restrict__ v, const float* __restrict__ beta)
{
    extern __shared__ float s[];
    float* sqn = s;                       // 32 x RSTR
    float* skn = sqn + C * RSTR;          // 32 x 128 (XOR-swizzled chunks)
    float* skb = skn + C * 128;           // 32 x RSTR
    float* sv  = skb + C * RSTR;          // 32 x RSTR
    float* sA  = sv  + C * RSTR;          // 32 x ASTR
    float* sP  = sA  + C * ASTR;          // 16 x 17 Schur temp

    const int nc  = blockIdx.x;
    const int t   = threadIdx.x;
    const int w   = t >> 5;
    const int lid = t & 31;
    const size_t base = (size_t)nc * (C * D);

    // ---- Phase 1: normalize + scale ----
    #pragma unroll
    for (int rr = 0; rr < 4; rr++) {
        const int r = w * 4 + rr;
        const float bet = __ldg(beta + (size_t)nc * C + r);
        float4 q4 = *(const float4*)(q + base + r * D + lid * 4);
        float4 k4 = *(const float4*)(k + base + r * D + lid * 4);
        float4 v4 = *(const float4*)(v + base + r * D + lid * 4);
        float qs = q4.x*q4.x + q4.y*q4.y + q4.z*q4.z + q4.w*q4.w;
        float ks = k4.x*k4.x + k4.y*k4.y + k4.z*k4.z + k4.w*k4.w;
        #pragma unroll
        for (int o = 16; o > 0; o >>= 1) {
            qs += __shfl_xor_sync(0xffffffffu, qs, o);
            ks += __shfl_xor_sync(0xffffffffu, ks, o);
        }
        const float qr = rsqrtf(qs + 1e-6f);
        const float kr = rsqrtf(ks + 1e-6f);
        float4 qn = make_float4(q4.x*qr, q4.y*qr, q4.z*qr, q4.w*qr);
        float4 kn = make_float4(k4.x*kr, k4.y*kr, k4.z*kr, k4.w*kr);
        float4 kb = make_float4(kn.x*bet, kn.y*bet, kn.z*bet, kn.w*bet);
        float4 vb = make_float4(v4.x*bet, v4.y*bet, v4.z*bet, v4.w*bet);
        *(float4*)(sqn + r * RSTR + lid * 4) = qn;
        *(float4*)(skn + r * 128 + ((lid ^ (r & 7)) << 2)) = kn;
        *(float4*)(skb + r * RSTR + lid * 4) = kb;
        *(float4*)(sv  + r * RSTR + lid * 4) = vb;
        *(float4*)(g_qn + base + r * D + lid * 4) = qn;
        // NOTE: g_kn written transposed (overlapped with phase 3a below)
    }
    __syncthreads();

    // ---- Phase 2: A (strict-lower, negated) and attn (lower incl diag) ----
    {
        const int j  = lid;
        const int i0 = w * 4;
        const int jx = (j & 7);
        unsigned long long A0=0,A1=0,A2=0,A3=0,T0=0,T1=0,T2=0,T3=0;
        const float* kjp = skn + j * 128;
        const float* b0p = skb + (i0+0) * RSTR;
        const float* b1p = skb + (i0+1) * RSTR;
        const float* b2p = skb + (i0+2) * RSTR;
        const float* b3p = skb + (i0+3) * RSTR;
        const float* q0p = sqn + (i0+0) * RSTR;
        const float* q1p = sqn + (i0+1) * RSTR;
        const float* q2p = sqn + (i0+2) * RSTR;
        const float* q3p = sqn + (i0+3) * RSTR;
        #pragma unroll 4
        for (int d = 0; d < D; d += 4) {
            ulonglong2 kj = *(const ulonglong2*)(kjp + ((((d >> 2) ^ jx)) << 2));
            ulonglong2 b0 = *(const ulonglong2*)(b0p + d);
            ulonglong2 b1 = *(const ulonglong2*)(b1p + d);
            ulonglong2 b2 = *(const ulonglong2*)(b2p + d);
            ulonglong2 b3 = *(const ulonglong2*)(b3p + d);
            fma2(A0, b0.x, kj.x); fma2(A0, b0.y, kj.y);
            fma2(A1, b1.x, kj.x); fma2(A1, b1.y, kj.y);
            fma2(A2, b2.x, kj.x); fma2(A2, b2.y, kj.y);
            fma2(A3, b3.x, kj.x); fma2(A3, b3.y, kj.y);
            ulonglong2 c0 = *(const ulonglong2*)(q0p + d);
            ulonglong2 c1 = *(const ulonglong2*)(q1p + d);
            ulonglong2 c2 = *(const ulonglong2*)(q2p + d);
            ulonglong2 c3 = *(const ulonglong2*)(q3p + d);
            fma2(T0, c0.x, kj.x); fma2(T0, c0.y, kj.y);
            fma2(T1, c1.x, kj.x); fma2(T1, c1.y, kj.y);
            fma2(T2, c2.x, kj.x); fma2(T2, c2.y, kj.y);
            fma2(T3, c3.x, kj.x); fma2(T3, c3.y, kj.y);
        }
        const float a0 = hadd2(A0), a1 = hadd2(A1), a2 = hadd2(A2), a3 = hadd2(A3);
        const float t0 = hadd2(T0), t1 = hadd2(T1), t2 = hadd2(T2), t3 = hadd2(T3);
        float* ga = g_attn + (size_t)nc * (C * C);
        sA[(i0+0)*ASTR + j] = (j < i0+0) ? -a0 : 0.f;
        sA[(i0+1)*ASTR + j] = (j < i0+1) ? -a1 : 0.f;
        sA[(i0+2)*ASTR + j] = (j < i0+2) ? -a2 : 0.f;
        sA[(i0+3)*ASTR + j] = (j < i0+3) ? -a3 : 0.f;
        ga[(i0+0)*C + j] = (j <= i0+0) ? t0 : 0.f;
        ga[(i0+1)*C + j] = (j <= i0+1) ? t1 : 0.f;
        ga[(i0+2)*C + j] = (j <= i0+2) ? t2 : 0.f;
        ga[(i0+3)*C + j] = (j <= i0+3) ? t3 : 0.f;
    }
    __syncthreads();

    // ---- Phase 3a (warps 0-1) || kT transpose store (warps 2-7) ----
    if (w < 2) {
        const int b0 = w * 16;
        const int j  = lid & 15;
        for (int i = 1; i < 16; i++) {
            float acc = 0.f;
            for (int kk = j + 1; kk < i; kk++)
                acc += sA[(b0+i)*ASTR + b0+kk] * sA[(b0+kk)*ASTR + b0+j];
            __syncwarp();
            if (lid < 16 && j < i) sA[(b0+i)*ASTR + b0+j] += acc;
            __syncwarp();
        }
        if (lid < 16) sA[(b0+j)*ASTR + b0+j] = 1.0f;
    } else {
        // g_kn[chunk][d][r] = kn[r][d] (coalesced STG); 192 threads cover 256 slots
        for (int idx = t - 64; idx < 256; idx += 192) {
            const int r4 = (idx & 7) * 4;
            const int d0 = idx >> 3;            // 0..31
            #pragma unroll
            for (int i = 0; i < 4; i++) {
                const int d = d0 + 32 * i;
                const int g = d >> 2, lo = d & 3;
                float4 kk;
                kk.x = skn[(r4+0) * 128 + ((g ^ ((r4+0) & 7)) << 2) + lo];
                kk.y = skn[(r4+1) * 128 + ((g ^ ((r4+1) & 7)) << 2) + lo];
                kk.z = skn[(r4+2) * 128 + ((g ^ ((r4+2) & 7)) << 2) + lo];
                kk.w = skn[(r4+3) * 128 + ((g ^ ((r4+3) & 7)) << 2) + lo];
                *(float4*)(g_kn + base + d * C + r4) = kk;
            }
        }
    }
    __syncthreads();

    // ---- Phase 3b: Schur combine  X21 = X22 * A21 * X11 ----
    {
        const int r = t >> 4;
        const int cc = t & 15;
        float acc = 0.f;
        #pragma unroll 4
        for (int e = 0; e < 16; e++)
            acc += sA[(16+r)*ASTR + e] * sA[e*ASTR + cc];
        sP[r * 17 + cc] = acc;
        __syncthreads();
        float acc2 = 0.f;
        #pragma unroll 4
        for (int e = 0; e < 16; e++)
            acc2 += sA[(16+r)*ASTR + 16+e] * sP[e * 17 + cc];
        sA[(16+r)*ASTR + cc] = acc2;
    }
    __syncthreads();

    // ---- Phase 4: u = inv@v , w = inv@kb ----
    {
        const int i  = t >> 3;
        const int dl = (t & 7) * 4;
        #pragma unroll
        for (int db = 0; db < 4; db++) {
            const int d = db * 32 + dl;
            unsigned long long au01=0, au23=0, aw01=0, aw23=0;
            #pragma unroll 4
            for (int j0 = 0; j0 < C; j0 += 4) {
                float4 a4 = *(const float4*)(sA + i*ASTR + j0);
                #pragma unroll
                for (int jj = 0; jj < 4; jj++) {
                    const float av = (&a4.x)[jj];
                    unsigned long long a2 = pk2(av);
                    ulonglong2 v2 = *(const ulonglong2*)(sv  + (j0+jj)*RSTR + d);
                    ulonglong2 b2 = *(const ulonglong2*)(skb + (j0+jj)*RSTR + d);
                    fma2(au01, a2, v2.x); fma2(au23, a2, v2.y);
                    fma2(aw01, a2, b2.x); fma2(aw23, a2, b2.y);
                }
            }
            float2 l, h;
            l = up2(au01); h = up2(au23);
            *(float4*)(g_u + base + i*D + d) = make_float4(l.x, l.y, h.x, h.y);
            l = up2(aw01); h = up2(aw23);
            *(float4*)(g_w + base + i*D + d) = make_float4(l.x, l.y, h.x, h.y);
        }
    }
}

// ---------------------------------------------------------------------------
// Scan kernel: R15 structure + persistent S accumulators in registers
// (phase 4 never re-reads sS; STS cumulative value) + float4 attn loads.
// ---------------------------------------------------------------------------
// tile buffer offsets (floats): q | kT(128x36) | w | u0 | attn
#define OQ  0
#define OKT (C * RSTR)                       // 4224
#define OW  (OKT + D * KTSTR)                // 8832
#define OU0 (OW + C * RSTR)                  // 13056
#define OAT (OU0 + C * ASTR)                 // 14208
#define SBUF (OAT + C * ASTR)                // 15360
#define PMAT (C * ASTR)                      // one 32x32 partial matrix

__device__ __forceinline__ void prefetch_chunk(
    uint32_t smb, int ci, int w, int lid, int t, int c, int v4, int v0,
    const float* gq, const float* gkT, const float* gw,
    const float* gu, const float* ga)
{
    const size_t cb = (size_t)ci * (C * D);
    #pragma unroll
    for (int rr = 0; rr < 4; rr++) {
        const int r = w * 4 + rr;
        const uint32_t off = (uint32_t)(r * RSTR + lid * 4) * 4u;
        cpa16(smb + (uint32_t)OQ * 4u + off, gq + cb + r * D + lid * 4);
        cpa16(smb + (uint32_t)OW * 4u + off, gw + cb + r * D + lid * 4);
    }
    #pragma unroll
    for (int i = 0; i < 4; i++) {
        const int idx = t + 256 * i;
        const int row = idx >> 3;            // 0..127
        const int c4  = (idx & 7) * 4;
        cpa16(smb + (uint32_t)(OKT + row * KTSTR + c4) * 4u,
              gkT + cb + row * C + c4);
    }
    cpa16(smb + (uint32_t)(OU0 + c * ASTR + v4) * 4u, gu + cb + c * D + v0 + v4);
    cpa16(smb + (uint32_t)(OAT + c * ASTR + v4) * 4u,
          ga + (size_t)ci * (C * C) + c * C + v4);
    asm volatile("cp.async.commit_group;");
}

__global__ void __launch_bounds__(256, 1) scan_kernel(float* __restrict__ out)
{
    extern __shared__ float s[];
    float* sS  = s;                         // 128 x VSLICE
    float* sb0 = sS + D * VSLICE;
    float* sb1 = sb0 + SBUF;
    float* sui = sb1 + SBUF;                // 32 x ASTR
    float* sPQ = sui + C * ASTR;            // 32 x ASTR (final q@S)
    float* sPP = sPQ + C * ASTR;            // 8 x PMAT partial matrices (4 U, 4 Q)

    const int bh  = blockIdx.y;
    const int v0  = blockIdx.x * VSLICE;
    const int t   = threadIdx.x;
    const int w   = t >> 5;
    const int lid = t & 31;
    const int v4  = (t & 7) * 4;
    const int r0  = ((t >> 3) & 7) * 4;     // rows r0..r0+3
    const int dq  = t >> 6;                 // d quarter 0..3
    const int c   = t >> 3;

    #pragma unroll
    for (int rr = 0; rr < 4; rr++)
        *(float4*)(sS + (rr * 256 + t) * 4) = make_float4(0.f, 0.f, 0.f, 0.f);

    const uint32_t smb0 = (uint32_t)__cvta_generic_to_shared(sb0);
    const uint32_t smb1 = (uint32_t)__cvta_generic_to_shared(sb1);

    const size_t bhb = (size_t)bh * LSEQ * D;
    const float* gq  = g_qn + bhb;
    const float* gkT = g_kn + bhb;
    const float* gw  = g_w  + bhb;
    const float* gu  = g_u  + bhb;
    const float* ga  = g_attn + (size_t)bh * NCHUNK * (C * C);

    prefetch_chunk(smb0, 0, w, lid, t, c, v4, v0, gq, gkT, gw, gu, ga);

    // persistent S accumulators: thread owns rows {c,c+32,c+64,c+96} x v4..v4+3
    unsigned long long SR0=0,SR1=0,SR2=0,SR3=0,SR4=0,SR5=0,SR6=0,SR7=0;

    for (int ci = 0; ci < NCHUNK; ci++) {
        float* B = (ci & 1) ? sb1 : sb0;
        const uint32_t smn = (ci & 1) ? smb0 : smb1;
        const float* sq  = B + OQ;
        const float* skT = B + OKT;
        const float* sw  = B + OW;
        const float* su0 = B + OU0;
        const float* sat = B + OAT;

        asm volatile("cp.async.wait_group 0;");
        __syncthreads();                    // tiles ready + prev S update done

        const int cn = (ci + 1 < NCHUNK) ? ci + 1 : ci;
        prefetch_chunk(smn, cn, w, lid, t, c, v4, v0, gq, gkT, gw, gu, ga);

        // ---- phase 2: quarter-d GEMV, 4 rows/thread; ALL quarters store ----
        {
            unsigned long long aU[4][2], aQ[4][2];
            #pragma unroll
            for (int r = 0; r < 4; r++) {
                aU[r][0]=0; aU[r][1]=0; aQ[r][0]=0; aQ[r][1]=0;
            }
            const int dbeg = dq * 32;
            const float* wp = sw + dbeg;
            const float* qp = sq + dbeg;
            const float* Sp = sS + dbeg * VSLICE + v4;
            #pragma unroll 2
            for (int dg = 0; dg < 32; dg += 4) {
                float4 wv[4], qv[4];
                #pragma unroll
                for (int r = 0; r < 4; r++) {
                    wv[r] = *(const float4*)(wp + (r0 + r) * RSTR + dg);
                    qv[r] = *(const float4*)(qp + (r0 + r) * RSTR + dg);
                }
                #pragma unroll
                for (int i = 0; i < 4; i++) {
                    ulonglong2 S2 = *(const ulonglong2*)(Sp + (dg + i) * VSLICE);
                    #pragma unroll
                    for (int r = 0; r < 4; r++) {
                        unsigned long long w2 = pk2((&wv[r].x)[i]);
                        unsigned long long q2 = pk2((&qv[r].x)[i]);
                        fma2(aU[r][0], w2, S2.x); fma2(aU[r][1], w2, S2.y);
                        fma2(aQ[r][0], q2, S2.x); fma2(aQ[r][1], q2, S2.y);
                    }
                }
            }
            float* PU = sPP + dq * PMAT;
            float* PQ = sPP + (4 + dq) * PMAT;
            #pragma unroll
            for (int r = 0; r < 4; r++) {
                float2 l, h;
                l = up2(aU[r][0]); h = up2(aU[r][1]);
                *(float4*)(PU + (r0 + r) * ASTR + v4) = make_float4(l.x, l.y, h.x, h.y);
                l = up2(aQ[r][0]); h = up2(aQ[r][1]);
                *(float4*)(PQ + (r0 + r) * ASTR + v4) = make_float4(l.x, l.y, h.x, h.y);
            }
        }
        __syncthreads();

        // ---- combine (ALL 256 threads): one (c, v4) each ----
        {
            float4 u0 = *(const float4*)(su0 + c * ASTR + v4);
            float4 aU = make_float4(0.f,0.f,0.f,0.f);
            float4 aQ = make_float4(0.f,0.f,0.f,0.f);
            #pragma unroll
            for (int p = 0; p < 4; p++) {
                float4 pu = *(const float4*)(sPP + p * PMAT + c * ASTR + v4);
                float4 pq = *(const float4*)(sPP + (4+p) * PMAT + c * ASTR + v4);
                aU.x += pu.x; aU.y += pu.y; aU.z += pu.z; aU.w += pu.w;
                aQ.x += pq.x; aQ.y += pq.y; aQ.z += pq.z; aQ.w += pq.w;
            }
            *(float4*)(sui + c * ASTR + v4) = make_float4(
                u0.x - aU.x, u0.y - aU.y, u0.z - aU.z, u0.w - aU.w);
            *(float4*)(sPQ + c * ASTR + v4) = aQ;
        }
        __syncthreads();

        // ---- fused phase 3+4: one e-loop; out + persistent S accumulate ----
        {
            float4 a0 = *(const float4*)(sPQ + c * ASTR + v4);
            unsigned long long o01 = pkf(a0.x, a0.y);
            unsigned long long o23 = pkf(a0.z, a0.w);
            #pragma unroll 2
            for (int e4 = 0; e4 < C; e4 += 4) {
                float4 kv0 = *(const float4*)(skT + (c      ) * KTSTR + e4);
                float4 kv1 = *(const float4*)(skT + (c +  32) * KTSTR + e4);
                float4 kv2 = *(const float4*)(skT + (c +  64) * KTSTR + e4);
                float4 kv3 = *(const float4*)(skT + (c +  96) * KTSTR + e4);
                float4 av4 = *(const float4*)(sat + c * ASTR + e4);
                #pragma unroll
                for (int ee = 0; ee < 4; ee++) {
                    const int e = e4 + ee;
                    ulonglong2 u2 = *(const ulonglong2*)(sui + e * ASTR + v4);
                    unsigned long long a2 = pk2((&av4.x)[ee]);
                    fma2(o01, a2, u2.x); fma2(o23, a2, u2.y);
                    unsigned long long k0 = pk2((&kv0.x)[ee]);
                    unsigned long long k1 = pk2((&kv1.x)[ee]);
                    unsigned long long k2 = pk2((&kv2.x)[ee]);
                    unsigned long long k3 = pk2((&kv3.x)[ee]);
                    fma2(SR0, k0, u2.x); fma2(SR1, k0, u2.y);
                    fma2(SR2, k1, u2.x); fma2(SR3, k1, u2.y);
                    fma2(SR4, k2, u2.x); fma2(SR5, k2, u2.y);
                    fma2(SR6, k3, u2.x); fma2(SR7, k3, u2.y);
                }
            }
            {
                float2 l = up2(o01), h = up2(o23);
                *(float4*)(out + bhb + (size_t)ci * (C * D) + c * D + v0 + v4) =
                    make_float4(l.x, l.y, h.x, h.y);
            }
            // write cumulative S to smem (no read needed)
            float2 l, h;
            l = up2(SR0); h = up2(SR1);
            *(float4*)(sS + (c      ) * VSLICE + v4) = make_float4(l.x, l.y, h.x, h.y);
            l = up2(SR2); h = up2(SR3);
            *(float4*)(sS + (c +  32) * VSLICE + v4) = make_float4(l.x, l.y, h.x, h.y);
            l = up2(SR4); h = up2(SR5);
            *(float4*)(sS + (c +  64) * VSLICE + v4) = make_float4(l.x, l.y, h.x, h.y);
            l = up2(SR6); h = up2(SR7);
            *(float4*)(sS + (c +  96) * VSLICE + v4) = make_float4(l.x, l.y, h.x, h.y);
        }
    }
}

// ---------------------------------------------------------------------------
extern "C" void kernel_launch(void* const* d_in, const int* in_sizes, int n_in,
                              void* d_out, int out_size)
{
    const float* q    = (const float*)d_in[0];
    const float* k    = (const float*)d_in[1];
    const float* v    = (const float*)d_in[2];
    const float* beta = (const float*)d_in[3];
    float* out = (float*)d_out;

    const size_t smemA = (size_t)(3 * C * RSTR + C * 128 + C * ASTR + 16 * 17)
                         * sizeof(float);
    const size_t smemB = (size_t)(D * VSLICE + 2 * SBUF + 2 * C * ASTR + 8 * PMAT)
                         * sizeof(float);

    cudaFuncSetAttribute(prep_kernel, cudaFuncAttributeMaxDynamicSharedMemorySize,
                         (int)smemA);
    cudaFuncSetAttribute(scan_kernel, cudaFuncAttributeMaxDynamicSharedMemorySize,
                         (int)smemB);

    prep_kernel<<<NC_TOTAL, 256, smemA>>>(q, k, v, beta);
    scan_kernel<<<dim3(NSPLIT, BH), 256, smemB>>>(out);
}